// round 1
// baseline (speedup 1.0000x reference)
#include <cuda_runtime.h>
#include <cstdint>
#include <cstddef>

#define T_STEPS 2048
#define NB      32
#define HDIM    256
#define G4H     1024
#define CLUSTER_SZ 8

// ---------------------------------------------------------------------------
// Scratch (device globals — no allocation allowed in kernel_launch)
// ---------------------------------------------------------------------------
__device__ float g_xw0[(size_t)NB * T_STEPS * G4H];   // 268 MB
__device__ float g_h0seq[(size_t)NB * T_STEPS * HDIM]; // 64 MB
__device__ float g_xw1[(size_t)NB * T_STEPS * G4H];   // 268 MB
__device__ float g_h1T[NB * HDIM];

// ---------------------------------------------------------------------------
// GEMM: out[M x 1024] = A[M x K] @ W[K x 1024] + bias   (M = 65536)
// Block tile 64x64, full-K in SMEM, 256 threads, 4x4 register tile.
// ---------------------------------------------------------------------------
template <int K>
__global__ __launch_bounds__(256)
void gemm_xw(const float* __restrict__ A, const float* __restrict__ W,
             const float* __restrict__ bias, float* __restrict__ out) {
    extern __shared__ float sm[];
    float* a_s = sm;             // [K][65]  (A tile, transposed, pad 65 -> conflict-free)
    float* w_s = sm + K * 65;    // [K][64]

    const int tid = threadIdx.x;
    const long m0 = (long)blockIdx.x * 64;
    const int  n0 = blockIdx.y * 64;

    // Load A tile (gmem-coalesced over k; STS stride 65 == 1 mod 32: conflict-free)
    for (int idx = tid; idx < 64 * K; idx += 256) {
        int r = idx / K;
        int k = idx - r * K;
        a_s[k * 65 + r] = A[(m0 + r) * K + k];
    }
    // Load W tile (coalesced rows of 64 floats)
    for (int idx = tid; idx < K * 64; idx += 256) {
        int k = idx >> 6, c = idx & 63;
        w_s[idx] = W[k * G4H + n0 + c];
    }
    __syncthreads();

    const int tn = (tid & 15) << 2;
    const int tm = (tid >> 4) << 2;

    float acc[4][4] = {{0.f}};

#pragma unroll 8
    for (int k = 0; k < K; k++) {
        const float* ap = a_s + k * 65 + tm;
        float a0 = ap[0], a1 = ap[1], a2 = ap[2], a3 = ap[3];
        float4 b = *reinterpret_cast<const float4*>(w_s + k * 64 + tn);
        acc[0][0] = fmaf(a0, b.x, acc[0][0]); acc[0][1] = fmaf(a0, b.y, acc[0][1]);
        acc[0][2] = fmaf(a0, b.z, acc[0][2]); acc[0][3] = fmaf(a0, b.w, acc[0][3]);
        acc[1][0] = fmaf(a1, b.x, acc[1][0]); acc[1][1] = fmaf(a1, b.y, acc[1][1]);
        acc[1][2] = fmaf(a1, b.z, acc[1][2]); acc[1][3] = fmaf(a1, b.w, acc[1][3]);
        acc[2][0] = fmaf(a2, b.x, acc[2][0]); acc[2][1] = fmaf(a2, b.y, acc[2][1]);
        acc[2][2] = fmaf(a2, b.z, acc[2][2]); acc[2][3] = fmaf(a2, b.w, acc[2][3]);
        acc[3][0] = fmaf(a3, b.x, acc[3][0]); acc[3][1] = fmaf(a3, b.y, acc[3][1]);
        acc[3][2] = fmaf(a3, b.z, acc[3][2]); acc[3][3] = fmaf(a3, b.w, acc[3][3]);
    }

    float4 bv = *reinterpret_cast<const float4*>(bias + n0 + tn);
#pragma unroll
    for (int i = 0; i < 4; i++) {
        float4 o;
        o.x = acc[i][0] + bv.x; o.y = acc[i][1] + bv.y;
        o.z = acc[i][2] + bv.z; o.w = acc[i][3] + bv.w;
        *reinterpret_cast<float4*>(out + (m0 + tm + i) * G4H + n0 + tn) = o;
    }
}

// ---------------------------------------------------------------------------
// LSTM recurrence. Cluster of 8 CTAs handles one batch-pair:
//   CTA (rank r) owns hidden units [r*32, r*32+32) and their 4 gate columns.
//   U slice resident in SMEM [128 cols][256 k] padded to 260 (conflict-free
//   LDS.128 over k). 128 threads: thread (gate g, unit u) computes the
//   2-batch dot products for its gate column. Warps 0/1 do the gate combine
//   (one batch each, c-state in registers) and push h to all 8 cluster CTAs
//   via DSMEM. One barrier.cluster per step; h double-buffered by parity.
// ---------------------------------------------------------------------------
__device__ __forceinline__ float sigmoidf_(float x) {
    return __fdividef(1.f, 1.f + __expf(-x));
}

#define CLUSTER_SYNC() do { \
    asm volatile("barrier.cluster.arrive.aligned;" ::: "memory"); \
    asm volatile("barrier.cluster.wait.aligned;"   ::: "memory"); \
} while (0)

template <bool STORE_SEQ>
__global__ __launch_bounds__(128, 1) __cluster_dims__(CLUSTER_SZ, 1, 1)
void lstm_rec(const float* __restrict__ xw, const float* __restrict__ U,
              float* __restrict__ out_seq, float* __restrict__ out_last) {
    extern __shared__ float sm[];
    float* w_s  = sm;                 // [128][260]
    float* hbuf = sm + 128 * 260;     // [2 parity][2 batch][256]
    float* zs   = hbuf + 2 * 2 * HDIM; // [4 gate][2 batch][32]

    const int tid = threadIdx.x;      // 128
    const int g   = tid >> 5;         // gate 0..3 (i,f,g,o)
    const int u   = tid & 31;         // unit within CTA slice

    uint32_t rank;
    asm("mov.u32 %0, %%cluster_ctarank;" : "=r"(rank));
    const int cid  = blockIdx.x >> 3; // cluster id = batch pair
    const int u0   = (int)rank * 32;
    const int b0   = cid * 2;
    const int gcol = g * HDIM + u0 + u;

    // Load U slice into SMEM transposed: w_s[c][k] = U[k][gate*256 + u0 + uu]
    // gmem reads: 32 consecutive floats per (k, gate) -> coalesced.
    for (int idx = tid; idx < 128 * HDIM; idx += 128) {
        int k = idx >> 7;
        int c = idx & 127;
        int col = (c >> 5) * HDIM + u0 + (c & 31);
        w_s[c * 260 + k] = U[k * G4H + col];
    }
    // Zero h double-buffer (+ zs)
    for (int idx = tid; idx < 2 * 2 * HDIM + 256; idx += 128) hbuf[idx] = 0.f;

    float cst = 0.f;  // cell state (valid in warps 0/1, lane = unit)

    // Everyone's hbuf must be zeroed before any peer DSMEM write lands.
    CLUSTER_SYNC();

    const uint32_t hbuf_b32 = (uint32_t)__cvta_generic_to_shared(hbuf);
    const float* w_row = w_s + (g * 32 + u) * 260;

    const size_t x0 = (size_t)b0 * T_STEPS * G4H + gcol;
    const size_t x1 = (size_t)(b0 + 1) * T_STEPS * G4H + gcol;

    // Prefetch xw for t = 0
    float xwa = xw[x0];
    float xwb = xw[x1];

    for (int t = 0; t < T_STEPS; t++) {
        const float xcur_a = xwa, xcur_b = xwb;
        if (t + 1 < T_STEPS) {  // prefetch next step (hidden behind the dot)
            xwa = xw[x0 + (size_t)(t + 1) * G4H];
            xwb = xw[x1 + (size_t)(t + 1) * G4H];
        }

        const int rd = (t + 1) & 1;  // h(t-1) lives in buffer[(t-1)&1]
        const float4* wr4 = reinterpret_cast<const float4*>(w_row);
        const float4* hp0 = reinterpret_cast<const float4*>(hbuf + rd * 2 * HDIM);
        const float4* hp1 = hp0 + (HDIM / 4);

        // 8 independent FMA chains (serial chain would be 512*4 cycles)
        float s00 = 0.f, s01 = 0.f, s02 = 0.f, s03 = 0.f;
        float s10 = 0.f, s11 = 0.f, s12 = 0.f, s13 = 0.f;
#pragma unroll 8
        for (int k4 = 0; k4 < HDIM / 4; k4++) {
            float4 w = wr4[k4];
            float4 p = hp0[k4];   // broadcast load (same addr across warp)
            float4 q = hp1[k4];
            s00 = fmaf(w.x, p.x, s00); s01 = fmaf(w.y, p.y, s01);
            s02 = fmaf(w.z, p.z, s02); s03 = fmaf(w.w, p.w, s03);
            s10 = fmaf(w.x, q.x, s10); s11 = fmaf(w.y, q.y, s11);
            s12 = fmaf(w.z, q.z, s12); s13 = fmaf(w.w, q.w, s13);
        }
        float acc0 = xcur_a + ((s00 + s01) + (s02 + s03));
        float acc1 = xcur_b + ((s10 + s11) + (s12 + s13));

        zs[g * 64 + u]      = acc0;   // [gate][batch][unit]
        zs[g * 64 + 32 + u] = acc1;
        __syncthreads();

        if (tid < 64) {  // warps 0/1: gate combine, one batch each
            const int b  = tid >> 5;
            const int uu = tid & 31;
            float zi = zs[0 * 64 + b * 32 + uu];
            float zf = zs[1 * 64 + b * 32 + uu];
            float zg = zs[2 * 64 + b * 32 + uu];
            float zo = zs[3 * 64 + b * 32 + uu];
            float iv = sigmoidf_(zi);
            float fv = sigmoidf_(zf);
            float ov = sigmoidf_(zo);
            cst = fmaf(fv, cst, iv * zg);  // linear candidate activation
            float h = ov * cst;            // linear output activation

            if (STORE_SEQ) {
                out_seq[((size_t)(b0 + b) * T_STEPS + t) * HDIM + u0 + uu] = h;
            } else if (t == T_STEPS - 1) {
                out_last[(b0 + b) * HDIM + u0 + uu] = h;
            }

            // Broadcast h(t) to all 8 cluster CTAs (write parity t&1)
            uint32_t laddr = hbuf_b32 +
                ((uint32_t)((t & 1) * 2 * HDIM + b * HDIM + u0 + uu) << 2);
#pragma unroll
            for (int r = 0; r < CLUSTER_SZ; r++) {
                uint32_t raddr;
                asm volatile("mapa.shared::cluster.u32 %0, %1, %2;"
                             : "=r"(raddr) : "r"(laddr), "r"(r));
                asm volatile("st.shared::cluster.f32 [%0], %1;"
                             :: "r"(raddr), "f"(h) : "memory");
            }
        }
        // release-arrive orders the DSMEM stores before peers' next-step reads
        CLUSTER_SYNC();
    }
}

// ---------------------------------------------------------------------------
// Final FC: out[32,1,128] = h1T[32,256] @ Wfc[256,128] + bfc
// ---------------------------------------------------------------------------
__global__ __launch_bounds__(128)
void fc_kernel(const float* __restrict__ h, const float* __restrict__ Wfc,
               const float* __restrict__ bfc, float* __restrict__ out) {
    const int b = blockIdx.x;
    const int j = threadIdx.x;
    const float* hb = h + b * HDIM;
    float acc = bfc[j];
#pragma unroll 16
    for (int k = 0; k < HDIM; k++)
        acc = fmaf(hb[k], Wfc[k * 128 + j], acc);
    out[b * 128 + j] = acc;
}

// ---------------------------------------------------------------------------
// Launch
// ---------------------------------------------------------------------------
#define GEMM128_SMEM ((128 * 65 + 128 * 64) * 4)   // 66048
#define GEMM256_SMEM ((256 * 65 + 256 * 64) * 4)   // 132096
#define REC_SMEM     ((128 * 260 + 2 * 2 * HDIM + 256) * 4)  // 138240

extern "C" void kernel_launch(void* const* d_in, const int* in_sizes, int n_in,
                              void* d_out, int out_size) {
    const float* x   = (const float*)d_in[0];
    const float* W0  = (const float*)d_in[1];
    const float* U0  = (const float*)d_in[2];
    const float* b0v = (const float*)d_in[3];
    const float* W1  = (const float*)d_in[4];
    const float* U1  = (const float*)d_in[5];
    const float* b1v = (const float*)d_in[6];
    const float* Wfc = (const float*)d_in[7];
    const float* bfc = (const float*)d_in[8];
    float* out = (float*)d_out;

    float *xw0, *h0seq, *xw1, *h1T;
    cudaGetSymbolAddress((void**)&xw0,   g_xw0);
    cudaGetSymbolAddress((void**)&h0seq, g_h0seq);
    cudaGetSymbolAddress((void**)&xw1,   g_xw1);
    cudaGetSymbolAddress((void**)&h1T,   g_h1T);

    // idempotent, not a stream op — safe under graph capture
    cudaFuncSetAttribute(gemm_xw<128>, cudaFuncAttributeMaxDynamicSharedMemorySize, GEMM128_SMEM);
    cudaFuncSetAttribute(gemm_xw<256>, cudaFuncAttributeMaxDynamicSharedMemorySize, GEMM256_SMEM);
    cudaFuncSetAttribute(lstm_rec<true>,  cudaFuncAttributeMaxDynamicSharedMemorySize, REC_SMEM);
    cudaFuncSetAttribute(lstm_rec<false>, cudaFuncAttributeMaxDynamicSharedMemorySize, REC_SMEM);

    const long M = (long)NB * T_STEPS;  // 65536 rows

    // Layer 0 input projection: xw0 = x @ W0 + b0
    gemm_xw<128><<<dim3((unsigned)(M / 64), G4H / 64), 256, GEMM128_SMEM>>>(x, W0, b0v, xw0);
    // Layer 0 recurrence (store full sequence)
    lstm_rec<true><<<NB / 2 * CLUSTER_SZ, 128, REC_SMEM>>>(xw0, U0, h0seq, nullptr);
    // Layer 1 input projection: xw1 = h0seq @ W1 + b1
    gemm_xw<256><<<dim3((unsigned)(M / 64), G4H / 64), 256, GEMM256_SMEM>>>(h0seq, W1, b1v, xw1);
    // Layer 1 recurrence (store last h only)
    lstm_rec<false><<<NB / 2 * CLUSTER_SZ, 128, REC_SMEM>>>(xw1, U1, nullptr, h1T);
    // FC head
    fc_kernel<<<NB, 128>>>(h1T, Wfc, bfc, out);
}

// round 2
// speedup vs baseline: 1.0921x; 1.0921x over previous
#include <cuda_runtime.h>
#include <cstdint>
#include <cstddef>

#define T_STEPS 2048
#define NB      32
#define HDIM    256
#define G4H     1024
#define CLUSTER_SZ 8

// ---------------------------------------------------------------------------
// Scratch (device globals — no allocation allowed in kernel_launch)
// ---------------------------------------------------------------------------
__device__ float g_xw0[(size_t)NB * T_STEPS * G4H];    // 268 MB
__device__ float g_h0seq[(size_t)NB * T_STEPS * HDIM]; // 64 MB
__device__ float g_xw1[(size_t)NB * T_STEPS * G4H];    // 268 MB
__device__ float g_h1T[NB * HDIM];

// ---------------------------------------------------------------------------
// Packed fp32x2 helpers (Blackwell FFMA2 path — ptxas won't auto-fuse)
// ---------------------------------------------------------------------------
__device__ __forceinline__ uint64_t fma_x2(uint64_t a, uint64_t b, uint64_t c) {
    uint64_t d;
    asm("fma.rn.f32x2 %0, %1, %2, %3;" : "=l"(d) : "l"(a), "l"(b), "l"(c));
    return d;
}
__device__ __forceinline__ uint64_t pack2(float x, float y) {
    uint64_t d;
    asm("mov.b64 %0, {%1, %2};" : "=l"(d) : "f"(x), "f"(y));
    return d;
}
__device__ __forceinline__ void unpack2(uint64_t v, float& lo, float& hi) {
    asm("mov.b64 {%0, %1}, %2;" : "=f"(lo), "=f"(hi) : "l"(v));
}
// One LDS.128 producing two packed f32x2 values.
__device__ __forceinline__ void lds_v2u64(uint64_t& a, uint64_t& b, uint32_t addr) {
    asm volatile("ld.shared.v2.u64 {%0, %1}, [%2];" : "=l"(a), "=l"(b) : "r"(addr));
}

// ---------------------------------------------------------------------------
// GEMM: out[M x 1024] = A[M x K] @ W[K x 1024] + bias   (M = 65536)
// 64x64 block tile, K chunked by 128 (66 KB smem -> 3 CTAs/SM), 256 threads,
// 4x4 per-thread tile computed with packed FFMA2.
// ---------------------------------------------------------------------------
template <int K>
__global__ __launch_bounds__(256)
void gemm_xw(const float* __restrict__ A, const float* __restrict__ W,
             const float* __restrict__ bias, float* __restrict__ out) {
    extern __shared__ float sm[];
    float* a_s = sm;               // [128][65] transposed A tile (pad 65: conflict-free)
    float* w_s = sm + 128 * 65;    // [128][64]

    const int tid = threadIdx.x;
    const long m0 = (long)blockIdx.x * 64;
    const int  n0 = blockIdx.y * 64;

    const int tn = (tid & 15) << 2;
    const int tm = (tid >> 4) << 2;

    const uint32_t ws_b = (uint32_t)__cvta_generic_to_shared(w_s);

    uint64_t acc01[4], acc23[4];
#pragma unroll
    for (int i = 0; i < 4; i++) { acc01[i] = 0ull; acc23[i] = 0ull; }

    for (int k0 = 0; k0 < K; k0 += 128) {
        // A tile: coalesced over k (consecutive tid -> consecutive k);
        // STS banks = k mod 32 -> conflict-free.
        for (int idx = tid; idx < 64 * 128; idx += 256) {
            int r = idx >> 7;
            int k = idx & 127;
            a_s[k * 65 + r] = A[(m0 + r) * K + k0 + k];
        }
        // W tile: float4 loads, rows of 64 floats.
        for (int idx = tid; idx < 128 * 16; idx += 256) {
            int k = idx >> 4, c4 = idx & 15;
            *reinterpret_cast<float4*>(w_s + k * 64 + c4 * 4) =
                *reinterpret_cast<const float4*>(W + (size_t)(k0 + k) * G4H + n0 + c4 * 4);
        }
        __syncthreads();

#pragma unroll 8
        for (int k = 0; k < 128; k++) {
            const float* ap = a_s + k * 65 + tm;
            float a0 = ap[0], a1 = ap[1], a2 = ap[2], a3 = ap[3];
            uint64_t b01, b23;
            lds_v2u64(b01, b23, ws_b + (uint32_t)(k * 64 + tn) * 4u);
            uint64_t aa;
            aa = pack2(a0, a0);
            acc01[0] = fma_x2(aa, b01, acc01[0]); acc23[0] = fma_x2(aa, b23, acc23[0]);
            aa = pack2(a1, a1);
            acc01[1] = fma_x2(aa, b01, acc01[1]); acc23[1] = fma_x2(aa, b23, acc23[1]);
            aa = pack2(a2, a2);
            acc01[2] = fma_x2(aa, b01, acc01[2]); acc23[2] = fma_x2(aa, b23, acc23[2]);
            aa = pack2(a3, a3);
            acc01[3] = fma_x2(aa, b01, acc01[3]); acc23[3] = fma_x2(aa, b23, acc23[3]);
        }
        __syncthreads();
    }

    float4 bv = *reinterpret_cast<const float4*>(bias + n0 + tn);
#pragma unroll
    for (int i = 0; i < 4; i++) {
        float4 o;
        unpack2(acc01[i], o.x, o.y);
        unpack2(acc23[i], o.z, o.w);
        o.x += bv.x; o.y += bv.y; o.z += bv.z; o.w += bv.w;
        *reinterpret_cast<float4*>(out + (m0 + tm + i) * G4H + n0 + tn) = o;
    }
}

// ---------------------------------------------------------------------------
// LSTM recurrence. Cluster of 8 CTAs per batch-pair; CTA (rank r) owns hidden
// units [r*32, r*32+32) => 128 gate-columns. U slice resident in SMEM in a
// SWIZZLED layout w_s[gate][k4][lane] (float4): each LDS.128 reads 32
// consecutive 16B chunks -> conflict-free (this was 4-way conflicted before).
// Thread (g,u) computes the 2-batch dot(256) with packed FFMA2.
// Warps 0/1 combine gates (c-state in registers) and broadcast h(t) to all 8
// cluster CTAs via DSMEM; one barrier.cluster per step, h double-buffered.
// ---------------------------------------------------------------------------
__device__ __forceinline__ float sigmoidf_(float x) {
    return __fdividef(1.f, 1.f + __expf(-x));
}

#define CLUSTER_SYNC() do { \
    asm volatile("barrier.cluster.arrive.aligned;" ::: "memory"); \
    asm volatile("barrier.cluster.wait.aligned;"   ::: "memory"); \
} while (0)

#define WS_FLOATS   (128 * HDIM)          // 32768 floats = 128 KB
#define HBUF_OFF    WS_FLOATS             // [2 parity][2 batch][256]
#define ZS_OFF      (HBUF_OFF + 2 * 2 * HDIM)

template <bool STORE_SEQ>
__global__ __launch_bounds__(128, 1) __cluster_dims__(CLUSTER_SZ, 1, 1)
void lstm_rec(const float* __restrict__ xw, const float* __restrict__ U,
              float* __restrict__ out_seq, float* __restrict__ out_last) {
    extern __shared__ float sm[];
    float* w_s  = sm;
    float* hbuf = sm + HBUF_OFF;
    float* zs   = sm + ZS_OFF;

    const int tid = threadIdx.x;      // 128
    const int g   = tid >> 5;         // gate 0..3 (i,f,g,o) == warp id
    const int u   = tid & 31;         // unit within CTA slice == lane

    uint32_t rank;
    asm("mov.u32 %0, %%cluster_ctarank;" : "=r"(rank));
    const int cid  = blockIdx.x >> 3;
    const int u0   = (int)rank * 32;
    const int b0   = cid * 2;
    const int gcol = g * HDIM + u0 + u;

    // Load U slice into the swizzled SMEM layout:
    //   element (k, c) -> float index ((c>>5)*64 + (k>>2))*128 + (c&31)*4 + (k&3)
    // gmem side stays coalesced (consecutive tid -> consecutive column).
    for (int idx = tid; idx < 128 * HDIM; idx += 128) {
        int k = idx >> 7;          // 0..255
        int c = idx & 127;         // gate*32 + unit
        int col = (c >> 5) * HDIM + u0 + (c & 31);
        w_s[(((c >> 5) * 64 + (k >> 2)) << 7) + ((c & 31) << 2) + (k & 3)] =
            U[(size_t)k * G4H + col];
    }
    // Zero h double-buffer + zs
    for (int idx = tid; idx < 2 * 2 * HDIM + 256; idx += 128) hbuf[idx] = 0.f;

    float cst = 0.f;  // cell state (valid in warps 0/1, lane = unit)

    CLUSTER_SYNC();   // all peers' hbuf zeroed before any DSMEM write lands

    const uint32_t smem_b  = (uint32_t)__cvta_generic_to_shared(sm);
    const uint32_t hbuf_b  = smem_b + HBUF_OFF * 4u;
    // per-thread w base: g*32KB + u*16B, stride 512B per k4
    const uint32_t w_b     = smem_b + (uint32_t)g * 32768u + (uint32_t)u * 16u;

    const size_t x0 = (size_t)b0 * T_STEPS * G4H + gcol;
    const size_t x1 = (size_t)(b0 + 1) * T_STEPS * G4H + gcol;

    float xwa = xw[x0];
    float xwb = xw[x1];

    for (int t = 0; t < T_STEPS; t++) {
        const float xcur_a = xwa, xcur_b = xwb;
        if (t + 1 < T_STEPS) {
            xwa = xw[x0 + (size_t)(t + 1) * G4H];
            xwb = xw[x1 + (size_t)(t + 1) * G4H];
        }

        const int rd = (t + 1) & 1;  // h(t-1) parity
        const uint32_t h0_b = hbuf_b + (uint32_t)(rd * 2 * HDIM) * 4u;
        const uint32_t h1_b = h0_b + HDIM * 4u;

        uint64_t a01 = 0ull, a23 = 0ull, b01 = 0ull, b23 = 0ull;
#pragma unroll 16
        for (int k4 = 0; k4 < HDIM / 4; k4++) {
            uint64_t w01, w23, p01, p23, q01, q23;
            lds_v2u64(w01, w23, w_b + (uint32_t)k4 * 512u);  // conflict-free
            lds_v2u64(p01, p23, h0_b + (uint32_t)k4 * 16u);  // broadcast
            lds_v2u64(q01, q23, h1_b + (uint32_t)k4 * 16u);  // broadcast
            a01 = fma_x2(w01, p01, a01);
            a23 = fma_x2(w23, p23, a23);
            b01 = fma_x2(w01, q01, b01);
            b23 = fma_x2(w23, q23, b23);
        }
        float s0, s1, s2, s3, t0, t1, t2, t3;
        unpack2(a01, s0, s1); unpack2(a23, s2, s3);
        unpack2(b01, t0, t1); unpack2(b23, t2, t3);
        float acc0 = xcur_a + ((s0 + s1) + (s2 + s3));
        float acc1 = xcur_b + ((t0 + t1) + (t2 + t3));

        zs[g * 64 + u]      = acc0;   // [gate][batch][unit]
        zs[g * 64 + 32 + u] = acc1;
        __syncthreads();

        if (tid < 64) {  // warps 0/1: gate combine, one batch each
            const int b  = tid >> 5;
            const int uu = tid & 31;
            float zi = zs[0 * 64 + b * 32 + uu];
            float zf = zs[1 * 64 + b * 32 + uu];
            float zg = zs[2 * 64 + b * 32 + uu];
            float zo = zs[3 * 64 + b * 32 + uu];
            float iv = sigmoidf_(zi);
            float fv = sigmoidf_(zf);
            float ov = sigmoidf_(zo);
            cst = fmaf(fv, cst, iv * zg);  // linear candidate activation
            float h = ov * cst;            // linear output activation

            if (STORE_SEQ) {
                out_seq[((size_t)(b0 + b) * T_STEPS + t) * HDIM + u0 + uu] = h;
            } else if (t == T_STEPS - 1) {
                out_last[(b0 + b) * HDIM + u0 + uu] = h;
            }

            // Broadcast h(t) to all 8 cluster CTAs (write parity t&1)
            uint32_t laddr = hbuf_b +
                ((uint32_t)((t & 1) * 2 * HDIM + b * HDIM + u0 + uu) << 2);
#pragma unroll
            for (int r = 0; r < CLUSTER_SZ; r++) {
                uint32_t raddr;
                asm volatile("mapa.shared::cluster.u32 %0, %1, %2;"
                             : "=r"(raddr) : "r"(laddr), "r"(r));
                asm volatile("st.shared::cluster.f32 [%0], %1;"
                             :: "r"(raddr), "f"(h) : "memory");
            }
        }
        // release-arrive orders the DSMEM stores before peers' next-step reads
        CLUSTER_SYNC();
    }
}

// ---------------------------------------------------------------------------
// Final FC: out[32,1,128] = h1T[32,256] @ Wfc[256,128] + bfc
// ---------------------------------------------------------------------------
__global__ __launch_bounds__(128)
void fc_kernel(const float* __restrict__ h, const float* __restrict__ Wfc,
               const float* __restrict__ bfc, float* __restrict__ out) {
    const int b = blockIdx.x;
    const int j = threadIdx.x;
    const float* hb = h + b * HDIM;
    float acc = bfc[j];
#pragma unroll 16
    for (int k = 0; k < HDIM; k++)
        acc = fmaf(hb[k], Wfc[k * 128 + j], acc);
    out[b * 128 + j] = acc;
}

// ---------------------------------------------------------------------------
// Launch
// ---------------------------------------------------------------------------
#define GEMM_SMEM ((128 * 65 + 128 * 64) * 4)                 // 66048
#define REC_SMEM  ((WS_FLOATS + 2 * 2 * HDIM + 256) * 4)      // 136192

extern "C" void kernel_launch(void* const* d_in, const int* in_sizes, int n_in,
                              void* d_out, int out_size) {
    const float* x   = (const float*)d_in[0];
    const float* W0  = (const float*)d_in[1];
    const float* U0  = (const float*)d_in[2];
    const float* b0v = (const float*)d_in[3];
    const float* W1  = (const float*)d_in[4];
    const float* U1  = (const float*)d_in[5];
    const float* b1v = (const float*)d_in[6];
    const float* Wfc = (const float*)d_in[7];
    const float* bfc = (const float*)d_in[8];
    float* out = (float*)d_out;

    float *xw0, *h0seq, *xw1, *h1T;
    cudaGetSymbolAddress((void**)&xw0,   g_xw0);
    cudaGetSymbolAddress((void**)&h0seq, g_h0seq);
    cudaGetSymbolAddress((void**)&xw1,   g_xw1);
    cudaGetSymbolAddress((void**)&h1T,   g_h1T);

    cudaFuncSetAttribute(gemm_xw<128>, cudaFuncAttributeMaxDynamicSharedMemorySize, GEMM_SMEM);
    cudaFuncSetAttribute(gemm_xw<256>, cudaFuncAttributeMaxDynamicSharedMemorySize, GEMM_SMEM);
    cudaFuncSetAttribute(lstm_rec<true>,  cudaFuncAttributeMaxDynamicSharedMemorySize, REC_SMEM);
    cudaFuncSetAttribute(lstm_rec<false>, cudaFuncAttributeMaxDynamicSharedMemorySize, REC_SMEM);

    const long M = (long)NB * T_STEPS;  // 65536 rows

    gemm_xw<128><<<dim3((unsigned)(M / 64), G4H / 64), 256, GEMM_SMEM>>>(x, W0, b0v, xw0);
    lstm_rec<true><<<NB / 2 * CLUSTER_SZ, 128, REC_SMEM>>>(xw0, U0, h0seq, nullptr);
    gemm_xw<256><<<dim3((unsigned)(M / 64), G4H / 64), 256, GEMM_SMEM>>>(h0seq, W1, b1v, xw1);
    lstm_rec<false><<<NB / 2 * CLUSTER_SZ, 128, REC_SMEM>>>(xw1, U1, nullptr, h1T);
    fc_kernel<<<NB, 128>>>(h1T, Wfc, bfc, out);
}